// round 15
// baseline (speedup 1.0000x reference)
#include <cuda_runtime.h>
#include <cuda_bf16.h>
#include <cstdint>

#define N_NODES 30000
#define E_RAW   480000
#define E_TOT   (E_RAW + N_NODES)
#define DIM     512
#define HEADS   8
#define CH      64
#define NH      (N_NODES * HEADS)
#define TOTAL   ((long)N_NODES * DIM)

// ---------------- scratch (device globals; no allocations) ----------------
__device__ __nv_bfloat16 g_ahi[(size_t)N_NODES * DIM];
__device__ __nv_bfloat16 g_alo[(size_t)N_NODES * DIM];
__device__ __nv_bfloat16 g_b1hi[(size_t)DIM * DIM];
__device__ __nv_bfloat16 g_b1lo[(size_t)DIM * DIM];
__device__ __nv_bfloat16 g_b2hi[(size_t)DIM * DIM];
__device__ __nv_bfloat16 g_b2lo[(size_t)DIM * DIM];
__device__ float g_xp  [(size_t)N_NODES * DIM];
__device__ float g_as  [NH];
__device__ float g_ad  [NH];
__device__ int   g_deg [N_NODES];
__device__ int   g_cur [N_NODES];
__device__ int   g_rowptr[N_NODES + 1];
__device__ int   g_csrc[E_TOT];
__device__ int   g_w64;
#define SCAN_BLOCKS ((N_NODES + 1023) / 1024)
__device__ int   g_bsum[SCAN_BLOCKS];

// ---------------- PTX helpers (baseline ISA only; no 'a' features) ----------------
__device__ __forceinline__ uint32_t smem_u32(const void* p) {
    uint32_t a;
    asm("{ .reg .u64 t; cvta.to.shared.u64 t, %1; cvt.u32.u64 %0, t; }" : "=r"(a) : "l"(p));
    return a;
}
__device__ __forceinline__ void cp_async16(uint32_t saddr, const void* gaddr, int srcBytes) {
    asm volatile("cp.async.ca.shared.global [%0], [%1], 16, %2;"
                 :: "r"(saddr), "l"(gaddr), "r"(srcBytes) : "memory");
}
#define CP_COMMIT() asm volatile("cp.async.commit_group;" ::: "memory")
#define CP_WAIT2()  asm volatile("cp.async.wait_group 2;" ::: "memory")

__device__ __forceinline__ void ldsm_x4(uint32_t* r, uint32_t addr) {
    asm volatile("ldmatrix.sync.aligned.m8n8.x4.shared.b16 {%0,%1,%2,%3}, [%4];"
                 : "=r"(r[0]), "=r"(r[1]), "=r"(r[2]), "=r"(r[3]) : "r"(addr));
}
__device__ __forceinline__ void mma_16816(float* d, const uint32_t* a, const uint32_t* b) {
    asm volatile("mma.sync.aligned.m16n8k16.row.col.f32.bf16.bf16.f32 "
                 "{%0,%1,%2,%3}, {%4,%5,%6,%7}, {%8,%9}, {%0,%1,%2,%3};"
                 : "+f"(d[0]), "+f"(d[1]), "+f"(d[2]), "+f"(d[3])
                 : "r"(a[0]), "r"(a[1]), "r"(a[2]), "r"(a[3]), "r"(b[0]), "r"(b[1]));
}

// ---------------- threefry2x32 (bit-exact JAX, partitionable) ----------------
__host__ __device__ __forceinline__ uint32_t rotl32(uint32_t v, int r) {
    return (v << r) | (v >> (32 - r));
}
__host__ __device__ __forceinline__ void threefry2x32_fn(
    uint32_t k0, uint32_t k1, uint32_t x0, uint32_t x1, uint32_t& o0, uint32_t& o1)
{
    uint32_t ks2 = k0 ^ k1 ^ 0x1BD11BDAu;
    x0 += k0; x1 += k1;
#define TFR(r) { x0 += x1; x1 = rotl32(x1, r); x1 ^= x0; }
    TFR(13) TFR(15) TFR(26) TFR(6)   x0 += k1;  x1 += ks2 + 1u;
    TFR(17) TFR(29) TFR(16) TFR(24)  x0 += ks2; x1 += k0  + 2u;
    TFR(13) TFR(15) TFR(26) TFR(6)   x0 += k0;  x1 += k1  + 3u;
    TFR(17) TFR(29) TFR(16) TFR(24)  x0 += k1;  x1 += ks2 + 4u;
    TFR(13) TFR(15) TFR(26) TFR(6)   x0 += ks2; x1 += k0  + 5u;
#undef TFR
    o0 = x0; o1 = x1;
}

__device__ __forceinline__ float drop_elu(float v, long idx, uint32_t k0, uint32_t k1)
{
    uint32_t o0, o1;
    threefry2x32_fn(k0, k1, 0u, (uint32_t)idx, o0, o1);
    float u = __uint_as_float((((o0 ^ o1)) >> 9) | 0x3f800000u) - 1.0f;
    v = (u < 0.8f) ? v * 1.25f : 0.0f;
    return (v > 0.0f) ? v : expm1f(v);
}

// ---------------- edge dtype detection ----------------
__global__ void k_detect(const int* __restrict__ ei32)
{
    if (threadIdx.x == 0 && blockIdx.x == 0) {
        int w = 1;
        #pragma unroll 1
        for (int i = 0; i < 64; i++)
            if (ei32[2 * i + 1] != 0) { w = 0; break; }
        g_w64 = w;
    }
}
__device__ __forceinline__ void edge_endpoints(const int* __restrict__ ei32,
                                               int e, int& s, int& d)
{
    if (e >= E_RAW) { s = d = e - E_RAW; return; }
    if (g_w64) { s = ei32[2 * e]; d = ei32[2 * (E_RAW + e)]; }
    else       { s = ei32[e];     d = ei32[E_RAW + e]; }
}

// ---------------- CSR build ----------------
__global__ void k_zero()
{
    int i = blockIdx.x * blockDim.x + threadIdx.x;
    if (i < N_NODES) { g_deg[i] = 0; g_cur[i] = 0; }
}
__global__ void k_count(const int* __restrict__ ei32)
{
    int e = blockIdx.x * blockDim.x + threadIdx.x;
    if (e >= E_TOT) return;
    int sn, dn; edge_endpoints(ei32, e, sn, dn);
    atomicAdd(&g_deg[dn], 1);
}
__global__ void k_scan1()
{
    __shared__ int sh[1024];
    int tid = threadIdx.x;
    int i = blockIdx.x * 1024 + tid;
    int v = (i < N_NODES) ? g_deg[i] : 0;
    sh[tid] = v;
    __syncthreads();
    for (int off = 1; off < 1024; off <<= 1) {
        int t = (tid >= off) ? sh[tid - off] : 0;
        __syncthreads();
        sh[tid] += t;
        __syncthreads();
    }
    if (i < N_NODES) g_rowptr[i] = sh[tid] - v;
    if (tid == 1023) g_bsum[blockIdx.x] = sh[1023];
}
__global__ void k_scan2()
{
    int tid = threadIdx.x;
    int v = (tid < SCAN_BLOCKS) ? g_bsum[tid] : 0;
    int incl = v;
    #pragma unroll
    for (int off = 1; off < 32; off <<= 1) {
        int t = __shfl_up_sync(0xFFFFFFFFu, incl, off);
        if (tid >= off) incl += t;
    }
    if (tid < SCAN_BLOCKS) g_bsum[tid] = incl - v;
    if (tid == 31) g_rowptr[N_NODES] = incl;
}
__global__ void k_scan3()
{
    int i = blockIdx.x * blockDim.x + threadIdx.x;
    if (i < N_NODES) g_rowptr[i] += g_bsum[i >> 10];
}
__global__ void k_fill(const int* __restrict__ ei32)
{
    int e = blockIdx.x * blockDim.x + threadIdx.x;
    if (e >= E_TOT) return;
    int sn, dn; edge_endpoints(ei32, e, sn, dn);
    int pos = atomicAdd(&g_cur[dn], 1);
    g_csrc[g_rowptr[dn] + pos] = sn;
}

// ---------------- layer-1 input: dropout + ELU -> bf16 hi/lo split ----------------
__global__ void k_dropelu(const float* __restrict__ in, uint32_t k0, uint32_t k1)
{
    long t = (long)blockIdx.x * blockDim.x + threadIdx.x;
    long i0 = t * 4;
    if (i0 >= TOTAL) return;
    float4 xin = *(const float4*)(in + i0);
    float vv[4] = { xin.x, xin.y, xin.z, xin.w };
    uint32_t hiP[2], loP[2];
    #pragma unroll
    for (int p = 0; p < 2; p++) {
        __nv_bfloat16 h2[2], l2[2];
        #pragma unroll
        for (int e2 = 0; e2 < 2; e2++) {
            float v = drop_elu(vv[p * 2 + e2], i0 + p * 2 + e2, k0, k1);
            __nv_bfloat16 hi = __float2bfloat16(v);
            h2[e2] = hi;
            l2[e2] = __float2bfloat16(v - __bfloat162float(hi));
        }
        hiP[p] = ((uint32_t)*(uint16_t*)&h2[1] << 16) | *(uint16_t*)&h2[0];
        loP[p] = ((uint32_t)*(uint16_t*)&l2[1] << 16) | *(uint16_t*)&l2[0];
    }
    *(uint2*)(g_ahi + i0) = make_uint2(hiP[0], hiP[1]);
    *(uint2*)(g_alo + i0) = make_uint2(loP[0], loP[1]);
}

// ---------------- W -> transposed bf16 hi/lo split: B[n][k] = W[k][n] ----------------
__global__ void k_wsplit(const float* __restrict__ W, int which)
{
    __nv_bfloat16* bhi = which ? g_b2hi : g_b1hi;
    __nv_bfloat16* blo = which ? g_b2lo : g_b1lo;
    int i = blockIdx.x * blockDim.x + threadIdx.x;
    if (i >= DIM * DIM) return;
    int k = i >> 9, n = i & (DIM - 1);
    float w = W[i];
    __nv_bfloat16 hi = __float2bfloat16(w);
    __nv_bfloat16 lo = __float2bfloat16(w - __bfloat162float(hi));
    bhi[n * DIM + k] = hi;
    blo[n * DIM + k] = lo;
}

// ---------------- HMMA bf16-split GEMM + fused attention dots ----------------
#define ROWB   80
#define ARRB   10240              // 128 * 80
#define STAGEB 40960              // 4 * ARRB
#define STAGES 4
__global__ __launch_bounds__(256, 1) void k_mm(
    const float* __restrict__ asrc, const float* __restrict__ adst, int which, int M)
{
    const __nv_bfloat16* __restrict__ Bhi = which ? g_b2hi : g_b1hi;
    const __nv_bfloat16* __restrict__ Blo = which ? g_b2lo : g_b1lo;

    extern __shared__ char smem[];
    const uint32_t smBase = smem_u32(smem);
    const int tid = threadIdx.x;
    const int lane = tid & 31, wid = tid >> 5;
    const int wm = wid & 3, wn = wid >> 2;
    const int rowBase = blockIdx.y * 128, colBase = blockIdx.x * 128;

    float acc[2][8][4] = {};

    auto issue_stage = [&](int kb) {
        uint32_t base = smBase + (kb & 3) * STAGEB;
        #pragma unroll
        for (int q = 0; q < 8; q++) {
            int a = q >> 1;
            int cid = tid + (q & 1) * 256;
            int row = cid >> 2, kc = cid & 3;
            const __nv_bfloat16* src;
            long gr;
            bool ok = true;
            if (a == 0)      { src = g_ahi; gr = rowBase + row; ok = (gr < M); }
            else if (a == 1) { src = g_alo; gr = rowBase + row; ok = (gr < M); }
            else if (a == 2) { src = Bhi;   gr = colBase + row; }
            else             { src = Blo;   gr = colBase + row; }
            uint32_t sa = base + a * ARRB + row * ROWB + kc * 16;
            cp_async16(sa, src + gr * DIM + kb * 32 + kc * 8, ok ? 16 : 0);
        }
        CP_COMMIT();
    };

    issue_stage(0);
    issue_stage(1);
    issue_stage(2);

    const int li = lane & 7, grp = lane >> 3;
    const int aRow = li + (grp & 1) * 8;
    const int bRow = li + (grp >> 1) * 8;

    #pragma unroll 1
    for (int kb = 0; kb < 16; kb++) {
        CP_WAIT2();
        __syncthreads();
        if (kb + 3 < 16) issue_stage(kb + 3);
        else CP_COMMIT();

        uint32_t sA = smBase + (kb & 3) * STAGEB;
        #pragma unroll
        for (int ks = 0; ks < 2; ks++) {
            uint32_t ahi[2][4], alo[2][4], bhi[4][4], blo[4][4];
            int aChunk = ks * 2 + (grp >> 1);
            int bChunk = ks * 2 + (grp & 1);
            #pragma unroll
            for (int mt = 0; mt < 2; mt++) {
                uint32_t off = (uint32_t)(wm * 32 + mt * 16 + aRow) * ROWB + aChunk * 16;
                ldsm_x4(ahi[mt], sA + off);
                ldsm_x4(alo[mt], sA + ARRB + off);
            }
            #pragma unroll
            for (int p = 0; p < 4; p++) {
                uint32_t off = (uint32_t)(wn * 64 + p * 16 + bRow) * ROWB + bChunk * 16;
                ldsm_x4(bhi[p], sA + 2 * ARRB + off);
                ldsm_x4(blo[p], sA + 3 * ARRB + off);
            }
            #pragma unroll
            for (int mt = 0; mt < 2; mt++) {
                #pragma unroll
                for (int nt = 0; nt < 8; nt++) {
                    const uint32_t* bh = &bhi[nt >> 1][(nt & 1) * 2];
                    const uint32_t* bl = &blo[nt >> 1][(nt & 1) * 2];
                    float* d = acc[mt][nt];
                    mma_16816(d, ahi[mt], bh);
                    mma_16816(d, ahi[mt], bl);
                    mma_16816(d, alo[mt], bh);
                }
            }
        }
    }

    // ---- epilogue: store C + fused attention dots ----
    const int head = blockIdx.x * 2 + wn;
    const float* av = asrc + head * CH;
    const float* dv = adst + head * CH;
    const int q = lane >> 2, qt = lane & 3;

    #pragma unroll
    for (int mt = 0; mt < 2; mt++) {
        int r0 = rowBase + wm * 32 + mt * 16 + q;
        int r1 = r0 + 8;
        float s0 = 0.f, s1 = 0.f, t0 = 0.f, t1 = 0.f;
        #pragma unroll
        for (int nt = 0; nt < 8; nt++) {
            int lc = nt * 8 + qt * 2;
            float a0v = av[lc], a1v = av[lc + 1];
            float d0v = dv[lc], d1v = dv[lc + 1];
            float* d = acc[mt][nt];
            s0 += d[0] * a0v + d[1] * a1v;  t0 += d[0] * d0v + d[1] * d1v;
            s1 += d[2] * a0v + d[3] * a1v;  t1 += d[2] * d0v + d[3] * d1v;
            long cb = colBase + wn * 64 + lc;
            if (r0 < M) *(float2*)&g_xp[(long)r0 * DIM + cb] = make_float2(d[0], d[1]);
            if (r1 < M) *(float2*)&g_xp[(long)r1 * DIM + cb] = make_float2(d[2], d[3]);
        }
        #pragma unroll
        for (int o = 1; o < 4; o <<= 1) {
            s0 += __shfl_xor_sync(0xFFFFFFFFu, s0, o);
            s1 += __shfl_xor_sync(0xFFFFFFFFu, s1, o);
            t0 += __shfl_xor_sync(0xFFFFFFFFu, t0, o);
            t1 += __shfl_xor_sync(0xFFFFFFFFu, t1, o);
        }
        if (qt == 0) {
            if (r0 < M) { g_as[r0 * HEADS + head] = s0; g_ad[r0 * HEADS + head] = t0; }
            if (r1 < M) { g_as[r1 * HEADS + head] = s1; g_ad[r1 * HEADS + head] = t1; }
        }
    }
}

// ---------------- fused softmax + aggregation (+ layer-specific epilogue) ----------------
#define DCAP 128
__global__ void k_aggr(const float* __restrict__ bias, float* __restrict__ out,
                       int mode, uint32_t k0, uint32_t k1)
{
    __shared__ float s_ed[HEADS][DCAP];
    __shared__ int   s_sc[HEADS][DCAP];
    __shared__ float red[HEADS][CH];

    int dn = blockIdx.x;
    int h = threadIdx.x >> 5;
    int lane = threadIdx.x & 31;
    int row0 = g_rowptr[dn];
    int deg  = g_rowptr[dn + 1] - row0;
    float advl = g_ad[dn * HEADS + h];
    bool cached = (deg <= DCAP);

    float mx = -3.4e38f, sm = 0.0f;
    for (int j = lane; j < deg; j += 32) {
        int sn = g_csrc[row0 + j];
        float e = g_as[sn * HEADS + h] + advl;
        e = (e > 0.0f) ? e : 0.2f * e;
        if (cached) { s_sc[h][j] = sn; s_ed[h][j] = e; }
        if (e > mx) { sm = sm * expf(mx - e) + 1.0f; mx = e; }
        else        { sm += expf(e - mx); }
    }
    #pragma unroll
    for (int o = 16; o; o >>= 1) {
        float mo = __shfl_xor_sync(0xFFFFFFFFu, mx, o);
        float so = __shfl_xor_sync(0xFFFFFFFFu, sm, o);
        float M2 = fmaxf(mx, mo);
        sm = sm * expf(mx - M2) + so * expf(mo - M2);
        mx = M2;
    }
    float inv = 1.0f / (sm + 1e-16f);

    float ax = 0.0f, ay = 0.0f;
    if (cached) {
        __syncwarp();
        for (int j = lane; j < deg; j += 32)
            s_ed[h][j] = expf(s_ed[h][j] - mx) * inv;
        __syncwarp();
        #pragma unroll 8
        for (int t = 0; t < deg; t++) {
            float a  = s_ed[h][t];
            int   sc = s_sc[h][t];
            float2 v = *(const float2*)&g_xp[(long)sc * DIM + h * CH + lane * 2];
            ax = fmaf(a, v.x, ax);
            ay = fmaf(a, v.y, ay);
        }
    } else {
        for (int base = 0; base < deg; base += 32) {
            int j = base + lane;
            float alpha = 0.0f;
            int sn = 0;
            if (j < deg) {
                sn = g_csrc[row0 + j];
                float e = g_as[sn * HEADS + h] + advl;
                e = (e > 0.0f) ? e : 0.2f * e;
                alpha = expf(e - mx) * inv;
            }
            s_ed[h][lane] = alpha;
            s_sc[h][lane] = sn;
            __syncwarp();
            int cnt = min(32, deg - base);
            #pragma unroll 8
            for (int t = 0; t < cnt; t++) {
                float a  = s_ed[h][t];
                int   sc = s_sc[h][t];
                float2 v = *(const float2*)&g_xp[(long)sc * DIM + h * CH + lane * 2];
                ax = fmaf(a, v.x, ax);
                ay = fmaf(a, v.y, ay);
            }
            __syncwarp();
        }
    }

    if (mode == 0) {
        float res[2] = { ax, ay };
        #pragma unroll
        for (int e2 = 0; e2 < 2; e2++) {
            long idx = (long)dn * DIM + h * CH + lane * 2 + e2;
            float v = res[e2] + bias[(int)(idx & (DIM - 1))];
            v = drop_elu(v, idx, k0, k1);
            __nv_bfloat16 hi = __float2bfloat16(v);
            g_ahi[idx] = hi;
            g_alo[idx] = __float2bfloat16(v - __bfloat162float(hi));
        }
    } else {
        red[h][lane * 2]     = ax;
        red[h][lane * 2 + 1] = ay;
        __syncthreads();
        int c = threadIdx.x;
        if (c < CH) {
            float s = 0.0f;
            #pragma unroll
            for (int hh = 0; hh < HEADS; hh++) s += red[hh][c];
            out[dn * CH + c] = s * 0.125f + bias[c];
        }
    }
}

// ---------------- host orchestration ----------------
extern "C" void kernel_launch(void* const* d_in, const int* in_sizes, int n_in,
                              void* d_out, int out_size)
{
    const float* x   = (const float*)d_in[0];
    const int*   ei  = (const int*)d_in[1];
    const float* W1  = (const float*)d_in[2];
    const float* as1 = (const float*)d_in[3];
    const float* ad1 = (const float*)d_in[4];
    const float* b1  = (const float*)d_in[5];
    const float* W2  = (const float*)d_in[6];
    const float* as2 = (const float*)d_in[7];
    const float* ad2 = (const float*)d_in[8];
    const float* b2  = (const float*)d_in[9];
    float*       out = (float*)d_out;

    uint32_t k1a, k1b, k2a, k2b;
    threefry2x32_fn(0u, 42u, 0u, 0u, k1a, k1b);
    threefry2x32_fn(0u, 42u, 0u, 1u, k2a, k2b);

    const int SMEM_MM = STAGES * STAGEB;   // 163840, 1 CTA/SM
    cudaFuncSetAttribute(k_mm, cudaFuncAttributeMaxDynamicSharedMemorySize, SMEM_MM);

    const int vecBlocks  = (int)((TOTAL / 4 + 255) / 256);
    const int edgeBlocks = (E_TOT + 255) / 256;
    const int nodeBlocks = (N_NODES + 255) / 256;
    const int wBlocks    = (DIM * DIM + 255) / 256;
    dim3 gemmGrid(DIM / 128, (N_NODES + 127) / 128);

    cudaStream_t s2;
    cudaEvent_t evFork, evJoin;
    cudaStreamCreateWithFlags(&s2, cudaStreamNonBlocking);
    cudaEventCreateWithFlags(&evFork, cudaEventDisableTiming);
    cudaEventCreateWithFlags(&evJoin, cudaEventDisableTiming);

    cudaEventRecord(evFork, 0);
    cudaStreamWaitEvent(s2, evFork, 0);

    // Submission order puts k_mm at launch #4 (ncu's profiled slot):
    // #1 wsplitW1, #2 dropelu (main), #3 detect (side), #4 mm1 (main).
    k_wsplit<<<wBlocks, 256>>>(W1, 0);                    // #1
    k_dropelu<<<vecBlocks, 256>>>(x, k1a, k1b);           // #2
    k_detect<<<1, 32, 0, s2>>>(ei);                       // #3
    k_mm<<<gemmGrid, 256, SMEM_MM>>>(as1, ad1, 0, N_NODES); // #4  <-- profiled

    // ---- side stream: rest of CSR chain + W2 prep (concurrent with mm1) ----
    k_zero<<<nodeBlocks, 256, 0, s2>>>();
    k_count<<<edgeBlocks, 256, 0, s2>>>(ei);
    k_scan1<<<SCAN_BLOCKS, 1024, 0, s2>>>();
    k_scan2<<<1, 32, 0, s2>>>();
    k_scan3<<<nodeBlocks, 256, 0, s2>>>();
    k_fill<<<edgeBlocks, 256, 0, s2>>>(ei);
    k_wsplit<<<wBlocks, 256, 0, s2>>>(W2, 1);
    cudaEventRecord(evJoin, s2);

    // ---- main stream: join CSR branch, then aggregation + layer 2 ----
    cudaStreamWaitEvent(0, evJoin, 0);
    k_aggr<<<N_NODES, 256>>>(b1, nullptr, 0, k2a, k2b);
    k_mm<<<gemmGrid, 256, SMEM_MM>>>(as2, ad2, 1, N_NODES);
    k_aggr<<<N_NODES, 256>>>(b2, out, 1, 0u, 0u);
}

// round 17
// speedup vs baseline: 1.0464x; 1.0464x over previous
#include <cuda_runtime.h>
#include <cuda_bf16.h>
#include <cstdint>

#define N_NODES 30000
#define E_RAW   480000
#define E_TOT   (E_RAW + N_NODES)
#define DIM     512
#define HEADS   8
#define CH      64
#define NH      (N_NODES * HEADS)
#define TOTAL   ((long)N_NODES * DIM)

// ---------------- scratch (device globals; no allocations) ----------------
__device__ __nv_bfloat16 g_ahi[(size_t)N_NODES * DIM];
__device__ __nv_bfloat16 g_alo[(size_t)N_NODES * DIM];
__device__ __nv_bfloat16 g_b1hi[(size_t)DIM * DIM];
__device__ __nv_bfloat16 g_b1lo[(size_t)DIM * DIM];
__device__ __nv_bfloat16 g_b2hi[(size_t)DIM * DIM];
__device__ __nv_bfloat16 g_b2lo[(size_t)DIM * DIM];
__device__ float g_xp  [(size_t)N_NODES * DIM];
__device__ float g_as  [NH];
__device__ float g_ad  [NH];
__device__ int   g_deg [N_NODES];
__device__ int   g_cur [N_NODES];
__device__ int   g_rowptr[N_NODES + 1];
__device__ int   g_csrc[E_TOT];
__device__ int   g_w64;
#define SCAN_BLOCKS ((N_NODES + 1023) / 1024)
__device__ int   g_bsum[SCAN_BLOCKS];

// ---------------- PTX helpers (baseline ISA only; no 'a' features) ----------------
__device__ __forceinline__ uint32_t smem_u32(const void* p) {
    uint32_t a;
    asm("{ .reg .u64 t; cvta.to.shared.u64 t, %1; cvt.u32.u64 %0, t; }" : "=r"(a) : "l"(p));
    return a;
}
__device__ __forceinline__ void cp_async16(uint32_t saddr, const void* gaddr, int srcBytes) {
    asm volatile("cp.async.ca.shared.global [%0], [%1], 16, %2;"
                 :: "r"(saddr), "l"(gaddr), "r"(srcBytes) : "memory");
}
#define CP_COMMIT() asm volatile("cp.async.commit_group;" ::: "memory")
#define CP_WAIT2()  asm volatile("cp.async.wait_group 2;" ::: "memory")

__device__ __forceinline__ void ldsm_x4(uint32_t* r, uint32_t addr) {
    asm volatile("ldmatrix.sync.aligned.m8n8.x4.shared.b16 {%0,%1,%2,%3}, [%4];"
                 : "=r"(r[0]), "=r"(r[1]), "=r"(r[2]), "=r"(r[3]) : "r"(addr));
}
__device__ __forceinline__ void mma_16816(float* d, const uint32_t* a, const uint32_t* b) {
    asm volatile("mma.sync.aligned.m16n8k16.row.col.f32.bf16.bf16.f32 "
                 "{%0,%1,%2,%3}, {%4,%5,%6,%7}, {%8,%9}, {%0,%1,%2,%3};"
                 : "+f"(d[0]), "+f"(d[1]), "+f"(d[2]), "+f"(d[3])
                 : "r"(a[0]), "r"(a[1]), "r"(a[2]), "r"(a[3]), "r"(b[0]), "r"(b[1]));
}

// ---------------- threefry2x32 (bit-exact JAX, partitionable) ----------------
__host__ __device__ __forceinline__ uint32_t rotl32(uint32_t v, int r) {
    return (v << r) | (v >> (32 - r));
}
__host__ __device__ __forceinline__ void threefry2x32_fn(
    uint32_t k0, uint32_t k1, uint32_t x0, uint32_t x1, uint32_t& o0, uint32_t& o1)
{
    uint32_t ks2 = k0 ^ k1 ^ 0x1BD11BDAu;
    x0 += k0; x1 += k1;
#define TFR(r) { x0 += x1; x1 = rotl32(x1, r); x1 ^= x0; }
    TFR(13) TFR(15) TFR(26) TFR(6)   x0 += k1;  x1 += ks2 + 1u;
    TFR(17) TFR(29) TFR(16) TFR(24)  x0 += ks2; x1 += k0  + 2u;
    TFR(13) TFR(15) TFR(26) TFR(6)   x0 += k0;  x1 += k1  + 3u;
    TFR(17) TFR(29) TFR(16) TFR(24)  x0 += k1;  x1 += ks2 + 4u;
    TFR(13) TFR(15) TFR(26) TFR(6)   x0 += ks2; x1 += k0  + 5u;
#undef TFR
    o0 = x0; o1 = x1;
}

__device__ __forceinline__ float drop_elu(float v, long idx, uint32_t k0, uint32_t k1)
{
    uint32_t o0, o1;
    threefry2x32_fn(k0, k1, 0u, (uint32_t)idx, o0, o1);
    float u = __uint_as_float((((o0 ^ o1)) >> 9) | 0x3f800000u) - 1.0f;
    v = (u < 0.8f) ? v * 1.25f : 0.0f;
    return (v > 0.0f) ? v : expm1f(v);
}

// ---------------- edge dtype detection ----------------
__global__ void k_detect(const int* __restrict__ ei32)
{
    if (threadIdx.x == 0 && blockIdx.x == 0) {
        int w = 1;
        #pragma unroll 1
        for (int i = 0; i < 64; i++)
            if (ei32[2 * i + 1] != 0) { w = 0; break; }
        g_w64 = w;
    }
}
__device__ __forceinline__ void edge_endpoints(const int* __restrict__ ei32,
                                               int e, int& s, int& d)
{
    if (e >= E_RAW) { s = d = e - E_RAW; return; }
    if (g_w64) { s = ei32[2 * e]; d = ei32[2 * (E_RAW + e)]; }
    else       { s = ei32[e];     d = ei32[E_RAW + e]; }
}

// ---------------- CSR build ----------------
__global__ void k_zero()
{
    int i = blockIdx.x * blockDim.x + threadIdx.x;
    if (i < N_NODES) { g_deg[i] = 0; g_cur[i] = 0; }
}
__global__ void k_count(const int* __restrict__ ei32)
{
    int e = blockIdx.x * blockDim.x + threadIdx.x;
    if (e >= E_TOT) return;
    int sn, dn; edge_endpoints(ei32, e, sn, dn);
    atomicAdd(&g_deg[dn], 1);
}
__global__ void k_scan1()
{
    __shared__ int sh[1024];
    int tid = threadIdx.x;
    int i = blockIdx.x * 1024 + tid;
    int v = (i < N_NODES) ? g_deg[i] : 0;
    sh[tid] = v;
    __syncthreads();
    for (int off = 1; off < 1024; off <<= 1) {
        int t = (tid >= off) ? sh[tid - off] : 0;
        __syncthreads();
        sh[tid] += t;
        __syncthreads();
    }
    if (i < N_NODES) g_rowptr[i] = sh[tid] - v;
    if (tid == 1023) g_bsum[blockIdx.x] = sh[1023];
}
__global__ void k_scan2()
{
    int tid = threadIdx.x;
    int v = (tid < SCAN_BLOCKS) ? g_bsum[tid] : 0;
    int incl = v;
    #pragma unroll
    for (int off = 1; off < 32; off <<= 1) {
        int t = __shfl_up_sync(0xFFFFFFFFu, incl, off);
        if (tid >= off) incl += t;
    }
    if (tid < SCAN_BLOCKS) g_bsum[tid] = incl - v;
    if (tid == 31) g_rowptr[N_NODES] = incl;
}
__global__ void k_scan3()
{
    int i = blockIdx.x * blockDim.x + threadIdx.x;
    if (i < N_NODES) g_rowptr[i] += g_bsum[i >> 10];
}
__global__ void k_fill(const int* __restrict__ ei32)
{
    int e = blockIdx.x * blockDim.x + threadIdx.x;
    if (e >= E_TOT) return;
    int sn, dn; edge_endpoints(ei32, e, sn, dn);
    int pos = atomicAdd(&g_cur[dn], 1);
    g_csrc[g_rowptr[dn] + pos] = sn;
}

// ---------------- layer-1 input: dropout + ELU -> bf16 hi/lo split ----------------
__global__ void k_dropelu(const float* __restrict__ in, uint32_t k0, uint32_t k1)
{
    long t = (long)blockIdx.x * blockDim.x + threadIdx.x;
    long i0 = t * 4;
    if (i0 >= TOTAL) return;
    float4 xin = *(const float4*)(in + i0);
    float vv[4] = { xin.x, xin.y, xin.z, xin.w };
    uint32_t hiP[2], loP[2];
    #pragma unroll
    for (int p = 0; p < 2; p++) {
        __nv_bfloat16 h2[2], l2[2];
        #pragma unroll
        for (int e2 = 0; e2 < 2; e2++) {
            float v = drop_elu(vv[p * 2 + e2], i0 + p * 2 + e2, k0, k1);
            __nv_bfloat16 hi = __float2bfloat16(v);
            h2[e2] = hi;
            l2[e2] = __float2bfloat16(v - __bfloat162float(hi));
        }
        hiP[p] = ((uint32_t)*(uint16_t*)&h2[1] << 16) | *(uint16_t*)&h2[0];
        loP[p] = ((uint32_t)*(uint16_t*)&l2[1] << 16) | *(uint16_t*)&l2[0];
    }
    *(uint2*)(g_ahi + i0) = make_uint2(hiP[0], hiP[1]);
    *(uint2*)(g_alo + i0) = make_uint2(loP[0], loP[1]);
}

// ---------------- W -> transposed bf16 hi/lo split: B[n][k] = W[k][n] ----------------
__global__ void k_wsplit(const float* __restrict__ W, int which)
{
    __nv_bfloat16* bhi = which ? g_b2hi : g_b1hi;
    __nv_bfloat16* blo = which ? g_b2lo : g_b1lo;
    int i = blockIdx.x * blockDim.x + threadIdx.x;
    if (i >= DIM * DIM) return;
    int k = i >> 9, n = i & (DIM - 1);
    float w = W[i];
    __nv_bfloat16 hi = __float2bfloat16(w);
    __nv_bfloat16 lo = __float2bfloat16(w - __bfloat162float(hi));
    bhi[n * DIM + k] = hi;
    blo[n * DIM + k] = lo;
}

// ---------------- HMMA bf16-split GEMM + fused attention dots ----------------
// 128x128 block, BK=32, 512 threads = 16 warps (4m x 4n), warp tile 32x32,
// mma.m16n8k16, cp.async 4-stage pipeline, 1 CTA/SM (smem-limited).
// A/B ldmatrix fragment mappings are the R7-validated ones (distinct formulas).
#define ROWB   80
#define ARRB   10240              // 128 * 80
#define STAGEB 40960              // 4 * ARRB
#define STAGES 4
__global__ __launch_bounds__(512, 1) void k_mm(
    const float* __restrict__ asrc, const float* __restrict__ adst, int which, int M)
{
    const __nv_bfloat16* __restrict__ Bhi = which ? g_b2hi : g_b1hi;
    const __nv_bfloat16* __restrict__ Blo = which ? g_b2lo : g_b1lo;

    extern __shared__ char smem[];
    __shared__ float sred[4][2][8][4];   // [wm][head_local][q][s0,s1,t0,t1]
    const uint32_t smBase = smem_u32(smem);
    const int tid = threadIdx.x;
    const int lane = tid & 31, wid = tid >> 5;
    const int wm = wid & 3, wn = wid >> 2;          // 4m x 4n warps
    const int rowBase = blockIdx.y * 128, colBase = blockIdx.x * 128;

    float acc[2][4][4] = {};

    auto issue_stage = [&](int kb) {
        uint32_t base = smBase + (kb & 3) * STAGEB;
        int row = tid >> 2, kc = tid & 3;           // 512 chunks per array
        #pragma unroll
        for (int a = 0; a < 4; a++) {
            const __nv_bfloat16* src;
            long gr;
            bool ok = true;
            if (a == 0)      { src = g_ahi; gr = rowBase + row; ok = (gr < M); }
            else if (a == 1) { src = g_alo; gr = rowBase + row; ok = (gr < M); }
            else if (a == 2) { src = Bhi;   gr = colBase + row; }
            else             { src = Blo;   gr = colBase + row; }
            uint32_t sa = base + a * ARRB + row * ROWB + kc * 16;
            cp_async16(sa, src + gr * DIM + kb * 32 + kc * 8, ok ? 16 : 0);
        }
        CP_COMMIT();
    };

    issue_stage(0);
    issue_stage(1);
    issue_stage(2);

    const int li = lane & 7, grp = lane >> 3;
    const int aRow = li + (grp & 1) * 8;            // A: rows split by grp&1, k by grp>>1
    const int bRow = li + (grp >> 1) * 8;           // B: rows split by grp>>1, k by grp&1

    #pragma unroll 1
    for (int kb = 0; kb < 16; kb++) {
        CP_WAIT2();
        __syncthreads();
        if (kb + 3 < 16) issue_stage(kb + 3);
        else CP_COMMIT();

        uint32_t sA = smBase + (kb & 3) * STAGEB;
        #pragma unroll
        for (int ks = 0; ks < 2; ks++) {
            uint32_t ahi[2][4], alo[2][4], bhi[2][4], blo[2][4];
            int aChunk = ks * 2 + (grp >> 1);
            int bChunk = ks * 2 + (grp & 1);
            #pragma unroll
            for (int mt = 0; mt < 2; mt++) {
                uint32_t off = (uint32_t)(wm * 32 + mt * 16 + aRow) * ROWB + aChunk * 16;
                ldsm_x4(ahi[mt], sA + off);
                ldsm_x4(alo[mt], sA + ARRB + off);
            }
            #pragma unroll
            for (int p = 0; p < 2; p++) {
                uint32_t off = (uint32_t)(wn * 32 + p * 16 + bRow) * ROWB + bChunk * 16;
                ldsm_x4(bhi[p], sA + 2 * ARRB + off);
                ldsm_x4(blo[p], sA + 3 * ARRB + off);
            }
            #pragma unroll
            for (int mt = 0; mt < 2; mt++) {
                #pragma unroll
                for (int nt = 0; nt < 4; nt++) {
                    const uint32_t* bh = &bhi[nt >> 1][(nt & 1) * 2];
                    const uint32_t* bl = &blo[nt >> 1][(nt & 1) * 2];
                    float* d = acc[mt][nt];
                    mma_16816(d, ahi[mt], bh);
                    mma_16816(d, ahi[mt], bl);
                    mma_16816(d, alo[mt], bh);
                }
            }
        }
    }

    // ---- epilogue: store C + fused attention dots (2 warps combine per head) ----
    const int head_local = wn >> 1;                 // 0 or 1
    const int half = wn & 1;                        // which 32-col half of the head
    const int head = blockIdx.x * 2 + head_local;
    const float* av = asrc + head * CH + half * 32;
    const float* dv = adst + head * CH + half * 32;
    const int q = lane >> 2, qt = lane & 3;

    #pragma unroll
    for (int mt = 0; mt < 2; mt++) {
        int r0 = rowBase + wm * 32 + mt * 16 + q;
        int r1 = r0 + 8;
        float s0 = 0.f, s1 = 0.f, t0 = 0.f, t1 = 0.f;
        #pragma unroll
        for (int nt = 0; nt < 4; nt++) {
            int lc = nt * 8 + qt * 2;
            float a0v = av[lc], a1v = av[lc + 1];
            float d0v = dv[lc], d1v = dv[lc + 1];
            float* d = acc[mt][nt];
            s0 += d[0] * a0v + d[1] * a1v;  t0 += d[0] * d0v + d[1] * d1v;
            s1 += d[2] * a0v + d[3] * a1v;  t1 += d[2] * d0v + d[3] * d1v;
            long cb = colBase + wn * 32 + lc;
            if (r0 < M) *(float2*)&g_xp[(long)r0 * DIM + cb] = make_float2(d[0], d[1]);
            if (r1 < M) *(float2*)&g_xp[(long)r1 * DIM + cb] = make_float2(d[2], d[3]);
        }
        #pragma unroll
        for (int o = 1; o < 4; o <<= 1) {
            s0 += __shfl_xor_sync(0xFFFFFFFFu, s0, o);
            s1 += __shfl_xor_sync(0xFFFFFFFFu, s1, o);
            t0 += __shfl_xor_sync(0xFFFFFFFFu, t0, o);
            t1 += __shfl_xor_sync(0xFFFFFFFFu, t1, o);
        }
        if (qt == 0 && half == 0) {
            sred[wm][head_local][q][0] = s0;
            sred[wm][head_local][q][1] = s1;
            sred[wm][head_local][q][2] = t0;
            sred[wm][head_local][q][3] = t1;
        }
        __syncthreads();
        if (qt == 0 && half == 1) {
            s0 += sred[wm][head_local][q][0];
            s1 += sred[wm][head_local][q][1];
            t0 += sred[wm][head_local][q][2];
            t1 += sred[wm][head_local][q][3];
            if (r0 < M) { g_as[r0 * HEADS + head] = s0; g_ad[r0 * HEADS + head] = t0; }
            if (r1 < M) { g_as[r1 * HEADS + head] = s1; g_ad[r1 * HEADS + head] = t1; }
        }
        __syncthreads();
    }
}

// ---------------- fused softmax + aggregation (+ layer-specific epilogue) ----------------
#define DCAP 128
__global__ void k_aggr(const float* __restrict__ bias, float* __restrict__ out,
                       int mode, uint32_t k0, uint32_t k1)
{
    __shared__ float s_ed[HEADS][DCAP];
    __shared__ int   s_sc[HEADS][DCAP];
    __shared__ float red[HEADS][CH];

    int dn = blockIdx.x;
    int h = threadIdx.x >> 5;
    int lane = threadIdx.x & 31;
    int row0 = g_rowptr[dn];
    int deg  = g_rowptr[dn + 1] - row0;
    float advl = g_ad[dn * HEADS + h];
    bool cached = (deg <= DCAP);

    float mx = -3.4e38f, sm = 0.0f;
    for (int j = lane; j < deg; j += 32) {
        int sn = g_csrc[row0 + j];
        float e = g_as[sn * HEADS + h] + advl;
        e = (e > 0.0f) ? e : 0.2f * e;
        if (cached) { s_sc[h][j] = sn; s_ed[h][j] = e; }
        if (e > mx) { sm = sm * expf(mx - e) + 1.0f; mx = e; }
        else        { sm += expf(e - mx); }
    }
    #pragma unroll
    for (int o = 16; o; o >>= 1) {
        float mo = __shfl_xor_sync(0xFFFFFFFFu, mx, o);
        float so = __shfl_xor_sync(0xFFFFFFFFu, sm, o);
        float M2 = fmaxf(mx, mo);
        sm = sm * expf(mx - M2) + so * expf(mo - M2);
        mx = M2;
    }
    float inv = 1.0f / (sm + 1e-16f);

    float ax = 0.0f, ay = 0.0f;
    if (cached) {
        __syncwarp();
        for (int j = lane; j < deg; j += 32)
            s_ed[h][j] = expf(s_ed[h][j] - mx) * inv;
        __syncwarp();
        #pragma unroll 4
        for (int t = 0; t < deg; t++) {
            float a  = s_ed[h][t];
            int   sc = s_sc[h][t];
            float2 v = *(const float2*)&g_xp[(long)sc * DIM + h * CH + lane * 2];
            ax = fmaf(a, v.x, ax);
            ay = fmaf(a, v.y, ay);
        }
    } else {
        for (int base = 0; base < deg; base += 32) {
            int j = base + lane;
            float alpha = 0.0f;
            int sn = 0;
            if (j < deg) {
                sn = g_csrc[row0 + j];
                float e = g_as[sn * HEADS + h] + advl;
                e = (e > 0.0f) ? e : 0.2f * e;
                alpha = expf(e - mx) * inv;
            }
            s_ed[h][lane] = alpha;
            s_sc[h][lane] = sn;
            __syncwarp();
            int cnt = min(32, deg - base);
            #pragma unroll 4
            for (int t = 0; t < cnt; t++) {
                float a  = s_ed[h][t];
                int   sc = s_sc[h][t];
                float2 v = *(const float2*)&g_xp[(long)sc * DIM + h * CH + lane * 2];
                ax = fmaf(a, v.x, ax);
                ay = fmaf(a, v.y, ay);
            }
            __syncwarp();
        }
    }

    if (mode == 0) {
        float res[2] = { ax, ay };
        #pragma unroll
        for (int e2 = 0; e2 < 2; e2++) {
            long idx = (long)dn * DIM + h * CH + lane * 2 + e2;
            float v = res[e2] + bias[(int)(idx & (DIM - 1))];
            v = drop_elu(v, idx, k0, k1);
            __nv_bfloat16 hi = __float2bfloat16(v);
            g_ahi[idx] = hi;
            g_alo[idx] = __float2bfloat16(v - __bfloat162float(hi));
        }
    } else {
        red[h][lane * 2]     = ax;
        red[h][lane * 2 + 1] = ay;
        __syncthreads();
        int c = threadIdx.x;
        if (c < CH) {
            float s = 0.0f;
            #pragma unroll
            for (int hh = 0; hh < HEADS; hh++) s += red[hh][c];
            out[dn * CH + c] = s * 0.125f + bias[c];
        }
    }
}

// ---------------- host orchestration ----------------
extern "C" void kernel_launch(void* const* d_in, const int* in_sizes, int n_in,
                              void* d_out, int out_size)
{
    const float* x   = (const float*)d_in[0];
    const int*   ei  = (const int*)d_in[1];
    const float* W1  = (const float*)d_in[2];
    const float* as1 = (const float*)d_in[3];
    const float* ad1 = (const float*)d_in[4];
    const float* b1  = (const float*)d_in[5];
    const float* W2  = (const float*)d_in[6];
    const float* as2 = (const float*)d_in[7];
    const float* ad2 = (const float*)d_in[8];
    const float* b2  = (const float*)d_in[9];
    float*       out = (float*)d_out;

    uint32_t k1a, k1b, k2a, k2b;
    threefry2x32_fn(0u, 42u, 0u, 0u, k1a, k1b);
    threefry2x32_fn(0u, 42u, 0u, 1u, k2a, k2b);

    const int SMEM_MM = STAGES * STAGEB;   // 163840, 1 CTA/SM
    cudaFuncSetAttribute(k_mm, cudaFuncAttributeMaxDynamicSharedMemorySize, SMEM_MM);

    const int vecBlocks  = (int)((TOTAL / 4 + 255) / 256);
    const int edgeBlocks = (E_TOT + 255) / 256;
    const int nodeBlocks = (N_NODES + 255) / 256;
    const int wBlocks    = (DIM * DIM + 255) / 256;
    dim3 gemmGrid(DIM / 128, (N_NODES + 127) / 128);

    cudaStream_t s2;
    cudaEvent_t evFork, evJoin;
    cudaStreamCreateWithFlags(&s2, cudaStreamNonBlocking);
    cudaEventCreateWithFlags(&evFork, cudaEventDisableTiming);
    cudaEventCreateWithFlags(&evJoin, cudaEventDisableTiming);

    cudaEventRecord(evFork, 0);
    cudaStreamWaitEvent(s2, evFork, 0);

    // mm1 kept at launch #4 (ncu's profiled slot).
    k_wsplit<<<wBlocks, 256>>>(W1, 0);                      // #1
    k_dropelu<<<vecBlocks, 256>>>(x, k1a, k1b);             // #2
    k_detect<<<1, 32, 0, s2>>>(ei);                         // #3
    k_mm<<<gemmGrid, 512, SMEM_MM>>>(as1, ad1, 0, N_NODES); // #4  <-- profiled

    // ---- side stream: rest of CSR chain + W2 prep (concurrent with mm1) ----
    k_zero<<<nodeBlocks, 256, 0, s2>>>();
    k_count<<<edgeBlocks, 256, 0, s2>>>(ei);
    k_scan1<<<SCAN_BLOCKS, 1024, 0, s2>>>();
    k_scan2<<<1, 32, 0, s2>>>();
    k_scan3<<<nodeBlocks, 256, 0, s2>>>();
    k_fill<<<edgeBlocks, 256, 0, s2>>>(ei);
    k_wsplit<<<wBlocks, 256, 0, s2>>>(W2, 1);
    cudaEventRecord(evJoin, s2);

    // ---- main stream: join CSR branch, then aggregation + layer 2 ----
    cudaStreamWaitEvent(0, evJoin, 0);
    k_aggr<<<N_NODES, 256>>>(b1, nullptr, 0, k2a, k2b);
    k_mm<<<gemmGrid, 512, SMEM_MM>>>(as2, ad2, 1, N_NODES);
    k_aggr<<<N_NODES, 256>>>(b2, out, 1, 0u, 0u);
}